// round 16
// baseline (speedup 1.0000x reference)
#include <cuda_runtime.h>
#include <cuda_fp16.h>
#include <cstdint>

#define ASTG 16384
#define BSTG 17408                 // 130 rows * 128B = 16640, padded
#define SMEM_TOTAL (4*ASTG + 2*BSTG)   // 100352 -> 2 CTAs/SM

// ---------------- device scratch ----------------
__device__ float g_T[256 * 256];
__device__ float g_scale[8 * 256];
__device__ __align__(16) __half g_wpack[36 * 2 * 8192];          // [chunk][ocT][8192] pre-swizzled fp16
__device__ __align__(16) __half g_xh[8 * 128 * 128 * 256];       // [b][h][w][ic] fp16, code folded

// ---------------- helpers ----------------
__device__ __forceinline__ uint32_t smem_u32(const void* p) {
    uint32_t a;
    asm("{ .reg .u64 t; cvta.to.shared.u64 t, %1; cvt.u32.u64 %0, t; }" : "=r"(a) : "l"(p));
    return a;
}
#define SWZ128(o) ((o) ^ (((o) >> 3) & 0x70))

__device__ __forceinline__ void cp16(uint32_t dst, const void* src, int sz) {
    asm volatile("cp.async.cg.shared.global [%0], [%1], 16, %2;\n"
                 :: "r"(dst), "l"(src), "r"(sz) : "memory");
}
#define CP_COMMIT() asm volatile("cp.async.commit_group;" ::: "memory")
#define CP_WAIT1()  asm volatile("cp.async.wait_group 1;" ::: "memory")

#define LDSM4(r0, r1, r2, r3, addr) \
    asm volatile("ldmatrix.sync.aligned.m8n8.x4.shared.b16 {%0,%1,%2,%3}, [%4];" \
                 : "=r"(r0), "=r"(r1), "=r"(r2), "=r"(r3) : "r"(addr))

#define MMA16816(c, a0, a1, a2, a3, b0, b1) \
    asm volatile("mma.sync.aligned.m16n8k16.row.col.f32.f16.f16.f32 " \
                 "{%0,%1,%2,%3}, {%4,%5,%6,%7}, {%8,%9}, {%0,%1,%2,%3};" \
                 : "+f"((c)[0]), "+f"((c)[1]), "+f"((c)[2]), "+f"((c)[3]) \
                 : "r"(a0), "r"(a1), "r"(a2), "r"(a3), "r"(b0), "r"(b1))

// ---------------- prep kernels ----------------
__global__ void pack_w_kernel(const float* __restrict__ w) {
    int id = blockIdx.x * 256 + threadIdx.x;   // 0 .. 589823
    int chunk = id >> 14;
    int kk    = (id >> 8) & 63;
    int oc    = id & 255;
    int ocT = oc >> 7, m = oc & 127;
    float v = w[(chunk * 64 + kk) * 256 + oc];
    int sw = SWZ128(m * 128 + kk * 2) >> 1;
    g_wpack[(chunk * 2 + ocT) * 8192 + sw] = __float2half(v);
    if (blockIdx.x < 256) {
        int idx = blockIdx.x * 256 + threadIdx.x;   // ic*256 + oc
        float s = 0.f;
#pragma unroll
        for (int tap = 0; tap < 9; tap++) { float t = w[tap * 65536 + idx]; s += t * t; }
        g_T[idx] = s;
    }
}

__global__ void scale_kernel(const float* __restrict__ code) {
    __shared__ float c2[256];
    int b = blockIdx.x, oc = threadIdx.x;
    float c = code[b * 256 + oc];
    c2[oc] = c * c;
    __syncthreads();
    float s = 0.f;
#pragma unroll 8
    for (int ic = 0; ic < 256; ic++) s += g_T[ic * 256 + oc] * c2[ic];
    const float wscale = 1.0f / 48.0f, wscale2 = 1.0f / 2304.0f;
    g_scale[b * 256 + oc] = wscale * rsqrtf(wscale2 * s + 1e-8f);
}

__global__ __launch_bounds__(256)
void xt_kernel(const float* __restrict__ x, const float* __restrict__ code) {
    __shared__ float st[64][129];
    int bh = blockIdx.x;
    int b = bh >> 7, h = bh & 127;
    int tid = threadIdx.x;
    const int icp = tid & 31;
    for (int sub = 0; sub < 4; sub++) {
        int icB = sub * 64;
#pragma unroll
        for (int i = 0; i < 8; i++) {
            int lin = tid + 256 * i;
            int r = lin >> 5, c4 = (lin & 31) * 4;
            float4 v = *(const float4*)&x[((size_t)(b * 256 + icB + r)) * 16384 + h * 128 + c4];
            st[r][c4 + 0] = v.x;
            st[r][c4 + 1] = v.y;
            st[r][c4 + 2] = v.z;
            st[r][c4 + 3] = v.w;
        }
        __syncthreads();
        int ic0 = icB + icp * 2;
        float c0 = __ldg(&code[b * 256 + ic0]);
        float c1 = __ldg(&code[b * 256 + ic0 + 1]);
#pragma unroll
        for (int i = 0; i < 16; i++) {
            int lin = tid + 256 * i;
            int w = lin >> 5;
            __half2 hv = __floats2half2_rn(st[icp * 2][w] * c0, st[icp * 2 + 1][w] * c1);
            *(__half2*)&g_xh[((size_t)bh * 128 + w) * 256 + ic0] = hv;
        }
        __syncthreads();
    }
}

// ---- main conv: 128 oc x 128 px, B halo reuse, ring-4 A, loads after compute ----
// iteration t=0..35: A chunk(t) = (t%9)*4 + t/9 ; B big-chunk bc=t/3

__device__ __forceinline__ void load_A(int chunk, uint32_t st, int tid, int ocT) {
    const __half* wsrc = g_wpack + ((size_t)chunk * 2 + ocT) * 8192;
#pragma unroll
    for (int i = 0; i < 4; i++) {
        int u = tid + i * 256;               // 0..1023
        cp16(st + u * 16, wsrc + u * 8, 16);
    }
}

__device__ __forceinline__ void load_B(int bc, uint32_t st, int b, int h, int tid) {
    int icB = (bc / 3) * 64;
    int dh  = bc % 3 - 1;
    int hh = h + dh;
    bool rok = (unsigned)hh < 128u;
    const __half* xrow = g_xh + ((size_t)(b * 128 + (rok ? hh : 0)) * 128) * 256 + icB;
#pragma unroll
    for (int i = 0; i < 5; i++) {
        int u = tid + i * 256;               // 0..1279
        if (u < 1040) {
            int r = u >> 3, j = u & 7;       // r in [0,130)
            int w = r - 1;
            bool ok = rok && ((unsigned)w < 128u);
            const __half* src = xrow + (size_t)(ok ? w : 0) * 256 + j * 8;
            cp16(st + SWZ128(r * 128 + j * 16), src, ok ? 16 : 0);
        }
    }
}

__global__ __launch_bounds__(256, 2)
void conv_mma_kernel(const float* __restrict__ bias, float* __restrict__ out) {
    extern __shared__ char smem[];
    uint32_t sb = smem_u32(smem);
    const int tid = threadIdx.x;
    const int lane = tid & 31, wid = tid >> 5;     // 8 warps: 4m x 2n
    const int bx = blockIdx.x;                     // (bh<<1) | ocT
    const int ocT = bx & 1;
    const int bh = bx >> 1;
    const int b = bh >> 7, h = bh & 127;

    const uint32_t aB0 = sb;                       // A ring: 4 x 16KB
    const uint32_t bB0 = sb + 4 * ASTG;            // B ring: 2 x 17KB

    const int mbase = (wid & 3) * 32;              // oc within 128
    const int nbase = (wid >> 2) * 64;             // pixel within 128
    const uint32_t xmA = (lane & 7) << 4;
    const uint32_t aksel = (lane >> 4) * 16;
    const uint32_t bksel = ((lane >> 3) & 1) * 16;
    const uint32_t arow0 = (uint32_t)(mbase + (lane & 15)) * 128;
    const uint32_t arow1 = arow0 + 16 * 128;
    const int rowc = nbase + (lane >> 4) * 8 + (lane & 7) + 1;   // halo base row (dw=0)

    float acc[2][8][4];
#pragma unroll
    for (int mi = 0; mi < 2; mi++)
#pragma unroll
        for (int nt = 0; nt < 8; nt++)
#pragma unroll
            for (int q = 0; q < 4; q++) acc[mi][nt][q] = 0.f;

    // prologue: group0 = {A0, B0}, group1 = {A1}
    load_A(0, aB0, tid, ocT);
    load_B(0, bB0, b, h, tid);
    CP_COMMIT();
    load_A(4, aB0 + ASTG, tid, ocT);               // chunkA(1) = 1*4 + 0
    CP_COMMIT();

    for (int t = 0; t < 36; t++) {
        CP_WAIT1();
        __syncthreads();

        // ---- compute first (loads issued after, off the critical path) ----
        const uint32_t Ab = aB0 + (t & 3) * ASTG;
        const uint32_t Bb = bB0 + ((t / 3) & 1) * BSTG;
        const int dw = t % 3 - 1;
        const int rw = rowc + dw;
        const uint32_t xmB = (uint32_t)(rw & 7) << 4;
        uint32_t brow[4];
#pragma unroll
        for (int nj = 0; nj < 4; nj++)
            brow[nj] = (uint32_t)(rw + nj * 16) * 128;

#pragma unroll
        for (int ks = 0; ks < 4; ks++) {
            const uint32_t kb = ks * 32;
            uint32_t bf[4][4];
#pragma unroll
            for (int nj = 0; nj < 4; nj++)
                LDSM4(bf[nj][0], bf[nj][1], bf[nj][2], bf[nj][3],
                      Bb + brow[nj] + ((kb + bksel) ^ xmB));
#pragma unroll
            for (int mi = 0; mi < 2; mi++) {
                uint32_t a0, a1, a2, a3;
                LDSM4(a0, a1, a2, a3,
                      Ab + (mi ? arow1 : arow0) + ((kb + aksel) ^ xmA));
#pragma unroll
                for (int nj = 0; nj < 4; nj++) {
                    MMA16816(acc[mi][nj * 2 + 0], a0, a1, a2, a3, bf[nj][0], bf[nj][1]);
                    MMA16816(acc[mi][nj * 2 + 1], a0, a1, a2, a3, bf[nj][2], bf[nj][3]);
                }
            }
        }

        // ---- issue next loads (ring-4 A makes this safe post-compute) ----
        if (t + 2 < 36) {
            int tn = t + 2;
            load_A((tn % 9) * 4 + tn / 9, aB0 + (tn & 3) * ASTG, tid, ocT);
        }
        if (t % 3 == 0 && (t / 3 + 1) < 12)
            load_B(t / 3 + 1, bB0 + ((t / 3 + 1) & 1) * BSTG, b, h, tid);
        CP_COMMIT();   // unconditional: keeps wait_group invariant at tail
    }

    // epilogue: demod scale + bias + LeakyReLU(0.2)*sqrt(2)
    const float ACT = 1.4142135623730951f;
    const int r0 = lane >> 2;
    const int cpix = (lane & 3) * 2;
#pragma unroll
    for (int mi = 0; mi < 2; mi++) {
        int ocb = ocT * 128 + mbase + mi * 16;
        int oc0 = ocb + r0, oc1 = oc0 + 8;
        float s0 = g_scale[b * 256 + oc0], bi0 = bias[oc0];
        float s1 = g_scale[b * 256 + oc1], bi1 = bias[oc1];
        float* o0 = out + ((size_t)(b * 256 + oc0)) * 16384 + h * 128;
        float* o1 = out + ((size_t)(b * 256 + oc1)) * 16384 + h * 128;
#pragma unroll
        for (int nt = 0; nt < 8; nt++) {
            int w = nbase + nt * 8 + cpix;
            float t0 = acc[mi][nt][0] * s0 + bi0;
            float t1 = acc[mi][nt][1] * s0 + bi0;
            float t2 = acc[mi][nt][2] * s1 + bi1;
            float t3 = acc[mi][nt][3] * s1 + bi1;
            float2 v0, v1;
            v0.x = (t0 >= 0.f ? t0 : 0.2f * t0) * ACT;
            v0.y = (t1 >= 0.f ? t1 : 0.2f * t1) * ACT;
            v1.x = (t2 >= 0.f ? t2 : 0.2f * t2) * ACT;
            v1.y = (t3 >= 0.f ? t3 : 0.2f * t3) * ACT;
            *(float2*)(o0 + w) = v0;
            *(float2*)(o1 + w) = v1;
        }
    }
}

// ---------------- launch ----------------
extern "C" void kernel_launch(void* const* d_in, const int* in_sizes, int n_in,
                              void* d_out, int out_size) {
    const float* x      = (const float*)d_in[0];
    const float* code   = (const float*)d_in[1];
    const float* weight = (const float*)d_in[2];
    const float* bias   = (const float*)d_in[3];
    float* out = (float*)d_out;

    cudaFuncSetAttribute(conv_mma_kernel, cudaFuncAttributeMaxDynamicSharedMemorySize, SMEM_TOTAL);

    pack_w_kernel<<<2304, 256>>>(weight);     // includes fused tsum
    scale_kernel<<<8, 256>>>(code);
    xt_kernel<<<1024, 256>>>(x, code);
    conv_mma_kernel<<<2048, 256, SMEM_TOTAL>>>(bias, out);  // launch #4 -> ncu slot
}

// round 17
// speedup vs baseline: 1.0209x; 1.0209x over previous
#include <cuda_runtime.h>
#include <cuda_fp16.h>
#include <cstdint>

#define ASTG 16384
#define BSTG 17408                 // 130 rows * 128B = 16640, padded
#define SMEM_TOTAL (3*ASTG + 2*BSTG)   // 83968 -> 2 CTAs/SM

// ---------------- device scratch ----------------
__device__ float g_T[256 * 256];
__device__ float g_scale[8 * 256];
__device__ __align__(16) __half g_wpack[36 * 2 * 8192];          // [chunk][ocT][8192] pre-swizzled fp16
__device__ __align__(16) __half g_xh[8 * 128 * 128 * 256];       // [b][h][w][ic] fp16, code folded

// ---------------- helpers ----------------
__device__ __forceinline__ uint32_t smem_u32(const void* p) {
    uint32_t a;
    asm("{ .reg .u64 t; cvta.to.shared.u64 t, %1; cvt.u32.u64 %0, t; }" : "=r"(a) : "l"(p));
    return a;
}
#define SWZ128(o) ((o) ^ (((o) >> 3) & 0x70))

__device__ __forceinline__ void cp16(uint32_t dst, const void* src, int sz) {
    asm volatile("cp.async.cg.shared.global [%0], [%1], 16, %2;\n"
                 :: "r"(dst), "l"(src), "r"(sz) : "memory");
}
#define CP_COMMIT() asm volatile("cp.async.commit_group;" ::: "memory")
#define CP_WAIT1()  asm volatile("cp.async.wait_group 1;" ::: "memory")

#define LDSM4(r0, r1, r2, r3, addr) \
    asm volatile("ldmatrix.sync.aligned.m8n8.x4.shared.b16 {%0,%1,%2,%3}, [%4];" \
                 : "=r"(r0), "=r"(r1), "=r"(r2), "=r"(r3) : "r"(addr))

#define MMA16816(c, a0, a1, a2, a3, b0, b1) \
    asm volatile("mma.sync.aligned.m16n8k16.row.col.f32.f16.f16.f32 " \
                 "{%0,%1,%2,%3}, {%4,%5,%6,%7}, {%8,%9}, {%0,%1,%2,%3};" \
                 : "+f"((c)[0]), "+f"((c)[1]), "+f"((c)[2]), "+f"((c)[3]) \
                 : "r"(a0), "r"(a1), "r"(a2), "r"(a3), "r"(b0), "r"(b1))

// ---------------- prep kernels ----------------
__global__ void pack_w_kernel(const float* __restrict__ w) {
    int id = blockIdx.x * 256 + threadIdx.x;   // 0 .. 589823
    int chunk = id >> 14;
    int kk    = (id >> 8) & 63;
    int oc    = id & 255;
    int ocT = oc >> 7, m = oc & 127;
    float v = w[(chunk * 64 + kk) * 256 + oc];
    int sw = SWZ128(m * 128 + kk * 2) >> 1;
    g_wpack[(chunk * 2 + ocT) * 8192 + sw] = __float2half(v);
    if (blockIdx.x < 256) {
        int idx = blockIdx.x * 256 + threadIdx.x;   // ic*256 + oc
        float s = 0.f;
#pragma unroll
        for (int tap = 0; tap < 9; tap++) { float t = w[tap * 65536 + idx]; s += t * t; }
        g_T[idx] = s;
    }
}

__global__ void scale_kernel(const float* __restrict__ code) {
    __shared__ float c2[256];
    int b = blockIdx.x, oc = threadIdx.x;
    float c = code[b * 256 + oc];
    c2[oc] = c * c;
    __syncthreads();
    float s = 0.f;
#pragma unroll 8
    for (int ic = 0; ic < 256; ic++) s += g_T[ic * 256 + oc] * c2[ic];
    const float wscale = 1.0f / 48.0f, wscale2 = 1.0f / 2304.0f;
    g_scale[b * 256 + oc] = wscale * rsqrtf(wscale2 * s + 1e-8f);
}

__global__ __launch_bounds__(256)
void xt_kernel(const float* __restrict__ x, const float* __restrict__ code) {
    __shared__ float st[64][129];
    int bh = blockIdx.x;
    int b = bh >> 7, h = bh & 127;
    int tid = threadIdx.x;
    const int icp = tid & 31;
    for (int sub = 0; sub < 4; sub++) {
        int icB = sub * 64;
#pragma unroll
        for (int i = 0; i < 8; i++) {
            int lin = tid + 256 * i;
            int r = lin >> 5, c4 = (lin & 31) * 4;
            float4 v = *(const float4*)&x[((size_t)(b * 256 + icB + r)) * 16384 + h * 128 + c4];
            st[r][c4 + 0] = v.x;
            st[r][c4 + 1] = v.y;
            st[r][c4 + 2] = v.z;
            st[r][c4 + 3] = v.w;
        }
        __syncthreads();
        int ic0 = icB + icp * 2;
        float c0 = __ldg(&code[b * 256 + ic0]);
        float c1 = __ldg(&code[b * 256 + ic0 + 1]);
#pragma unroll
        for (int i = 0; i < 16; i++) {
            int lin = tid + 256 * i;
            int w = lin >> 5;
            __half2 hv = __floats2half2_rn(st[icp * 2][w] * c0, st[icp * 2 + 1][w] * c1);
            *(__half2*)&g_xh[((size_t)bh * 128 + w) * 256 + ic0] = hv;
        }
        __syncthreads();
    }
}

// ---- main conv: 128 oc x 128 px, 128 thr, 4 warps of 64x64, 2 CTAs/SM ----
// iteration t=0..35: A chunk(t) = (t%9)*4 + t/9 ; B big-chunk bc=t/3

__device__ __forceinline__ void load_A(int chunk, uint32_t st, int tid, int ocT) {
    const __half* wsrc = g_wpack + ((size_t)chunk * 2 + ocT) * 8192;
#pragma unroll
    for (int i = 0; i < 8; i++) {
        int u = tid + i * 128;               // 0..1023
        cp16(st + u * 16, wsrc + u * 8, 16);
    }
}

__device__ __forceinline__ void load_B(int bc, uint32_t st, int b, int h, int tid) {
    int icB = (bc / 3) * 64;
    int dh  = bc % 3 - 1;
    int hh = h + dh;
    bool rok = (unsigned)hh < 128u;
    const __half* xrow = g_xh + ((size_t)(b * 128 + (rok ? hh : 0)) * 128) * 256 + icB;
#pragma unroll
    for (int i = 0; i < 9; i++) {
        int u = tid + i * 128;               // 0..1151
        if (u < 1040) {
            int r = u >> 3, j = u & 7;       // r in [0,130)
            int w = r - 1;
            bool ok = rok && ((unsigned)w < 128u);
            const __half* src = xrow + (size_t)(ok ? w : 0) * 256 + j * 8;
            cp16(st + SWZ128(r * 128 + j * 16), src, ok ? 16 : 0);
        }
    }
}

__global__ __launch_bounds__(128, 2)
void conv_mma_kernel(const float* __restrict__ bias, float* __restrict__ out) {
    extern __shared__ char smem[];
    uint32_t sb = smem_u32(smem);
    const int tid = threadIdx.x;
    const int lane = tid & 31, wid = tid >> 5;     // 4 warps: 2m x 2n
    const int bx = blockIdx.x;                     // (bh<<1) | ocT
    const int ocT = bx & 1;
    const int bh = bx >> 1;
    const int b = bh >> 7, h = bh & 127;

    const uint32_t aB0 = sb;                       // A ring: 3 x 16KB
    const uint32_t bB0 = sb + 3 * ASTG;            // B ring: 2 x 17KB

    const int mbase = (wid & 1) * 64;              // oc within 128
    const int nbase = (wid >> 1) * 64;             // pixel within 128
    const uint32_t xmA = (lane & 7) << 4;
    const uint32_t aksel = (lane >> 4) * 16;
    const uint32_t bksel = ((lane >> 3) & 1) * 16;
    uint32_t arow[4];
#pragma unroll
    for (int mi = 0; mi < 4; mi++)
        arow[mi] = (uint32_t)(mbase + mi * 16 + (lane & 15)) * 128;
    const int rowc = nbase + (lane >> 4) * 8 + (lane & 7) + 1;   // halo base row (dw=0)

    float acc[4][8][4];
#pragma unroll
    for (int mi = 0; mi < 4; mi++)
#pragma unroll
        for (int nt = 0; nt < 8; nt++)
#pragma unroll
            for (int q = 0; q < 4; q++) acc[mi][nt][q] = 0.f;

    // prologue: group0 = {A0, B0}, group1 = {A1}
    load_A(0, aB0, tid, ocT);
    load_B(0, bB0, b, h, tid);
    CP_COMMIT();
    load_A(4, aB0 + ASTG, tid, ocT);               // chunkA(1) = 1*4 + 0
    CP_COMMIT();

    for (int t = 0; t < 36; t++) {
        CP_WAIT1();
        __syncthreads();
        // issue loads for t+2 (A) and, every 3rd iter, B(bc+1)
        if (t + 2 < 36) {
            int tn = t + 2;
            load_A((tn % 9) * 4 + tn / 9, aB0 + (tn % 3) * ASTG, tid, ocT);
        }
        if (t % 3 == 0 && (t / 3 + 1) < 12)
            load_B(t / 3 + 1, bB0 + ((t / 3 + 1) & 1) * BSTG, b, h, tid);
        CP_COMMIT();   // unconditional: keeps wait_group invariant at tail

        const uint32_t Ab = aB0 + (t % 3) * ASTG;
        const uint32_t Bb = bB0 + ((t / 3) & 1) * BSTG;
        const int dw = t % 3 - 1;
        const int rw = rowc + dw;
        const uint32_t xmB = (uint32_t)(rw & 7) << 4;
        uint32_t brow[4];
#pragma unroll
        for (int nj = 0; nj < 4; nj++)
            brow[nj] = (uint32_t)(rw + nj * 16) * 128;

#pragma unroll
        for (int ks = 0; ks < 4; ks++) {
            const uint32_t kb = ks * 32;
            uint32_t bf[4][4];
#pragma unroll
            for (int nj = 0; nj < 4; nj++)
                LDSM4(bf[nj][0], bf[nj][1], bf[nj][2], bf[nj][3],
                      Bb + brow[nj] + ((kb + bksel) ^ xmB));
#pragma unroll
            for (int mi = 0; mi < 4; mi++) {
                uint32_t a0, a1, a2, a3;
                LDSM4(a0, a1, a2, a3,
                      Ab + arow[mi] + ((kb + aksel) ^ xmA));
#pragma unroll
                for (int nj = 0; nj < 4; nj++) {
                    MMA16816(acc[mi][nj * 2 + 0], a0, a1, a2, a3, bf[nj][0], bf[nj][1]);
                    MMA16816(acc[mi][nj * 2 + 1], a0, a1, a2, a3, bf[nj][2], bf[nj][3]);
                }
            }
        }
    }

    // epilogue: demod scale + bias + LeakyReLU(0.2)*sqrt(2)
    const float ACT = 1.4142135623730951f;
    const int r0 = lane >> 2;
    const int cpix = (lane & 3) * 2;
#pragma unroll
    for (int mi = 0; mi < 4; mi++) {
        int ocb = ocT * 128 + mbase + mi * 16;
        int oc0 = ocb + r0, oc1 = oc0 + 8;
        float s0 = g_scale[b * 256 + oc0], bi0 = bias[oc0];
        float s1 = g_scale[b * 256 + oc1], bi1 = bias[oc1];
        float* o0 = out + ((size_t)(b * 256 + oc0)) * 16384 + h * 128;
        float* o1 = out + ((size_t)(b * 256 + oc1)) * 16384 + h * 128;
#pragma unroll
        for (int nt = 0; nt < 8; nt++) {
            int w = nbase + nt * 8 + cpix;
            float t0 = acc[mi][nt][0] * s0 + bi0;
            float t1 = acc[mi][nt][1] * s0 + bi0;
            float t2 = acc[mi][nt][2] * s1 + bi1;
            float t3 = acc[mi][nt][3] * s1 + bi1;
            float2 v0, v1;
            v0.x = (t0 >= 0.f ? t0 : 0.2f * t0) * ACT;
            v0.y = (t1 >= 0.f ? t1 : 0.2f * t1) * ACT;
            v1.x = (t2 >= 0.f ? t2 : 0.2f * t2) * ACT;
            v1.y = (t3 >= 0.f ? t3 : 0.2f * t3) * ACT;
            *(float2*)(o0 + w) = v0;
            *(float2*)(o1 + w) = v1;
        }
    }
}

// ---------------- launch ----------------
extern "C" void kernel_launch(void* const* d_in, const int* in_sizes, int n_in,
                              void* d_out, int out_size) {
    const float* x      = (const float*)d_in[0];
    const float* code   = (const float*)d_in[1];
    const float* weight = (const float*)d_in[2];
    const float* bias   = (const float*)d_in[3];
    float* out = (float*)d_out;

    cudaFuncSetAttribute(conv_mma_kernel, cudaFuncAttributeMaxDynamicSharedMemorySize, SMEM_TOTAL);

    pack_w_kernel<<<2304, 256>>>(weight);     // includes fused tsum
    scale_kernel<<<8, 256>>>(code);
    xt_kernel<<<1024, 256>>>(x, code);
    conv_mma_kernel<<<2048, 128, SMEM_TOTAL>>>(bias, out);  // launch #4 -> ncu slot
}